// round 3
// baseline (speedup 1.0000x reference)
#include <cuda_runtime.h>
#include <cstdint>
#include <math.h>

#define CDIV(a,b) (((a)+(b)-1)/(b))

// ---------------- scratch (static device globals; no runtime alloc) ----------------
__device__ float g_xA [3137*8*512];
__device__ float g_xB [3137*8*512];
__device__ float g_ln [3137*8*512];
__device__ float g_att[3137*8*512];
__device__ float g_qkv[3137*8*1536];
__device__ float g_h  [3137*8*2048];   // also im2col scratch (needs 25088*768 < size)
__device__ int   g_idx[8*8*196*16];
__device__ float g_wT [768*512];

static const int SPAT_SMEM = (2*196*68 + 8*196 + 8*64) * 4;  // 114944 B

// ---------------- SGEMM: C[M,N] = A[M,K] @ B[K,N] + bias (+C if ACCUM) (ReLU opt) ----
// A row-major MxK, B row-major KxN, C row-major MxN. N % 128 == 0, K % 8 == 0.
template<bool ACCUM, bool RELU>
__global__ __launch_bounds__(256) void sgemm(const float* __restrict__ A,
    const float* __restrict__ Bm, const float* __restrict__ bias,
    float* __restrict__ Cm, int M, int N, int K)
{
    __shared__ float As[8][128];
    __shared__ float Bs[8][128];
    int tid = threadIdx.x;
    int bm = blockIdx.y * 128, bn = blockIdx.x * 128;
    int tr = (tid >> 4) << 3;       // 0..120
    int tc = (tid & 15) << 3;       // 0..120
    int arow = tid >> 1, acol = (tid & 1) << 2;
    int brow = tid >> 5, bcol = (tid & 31) << 2;
    float acc[8][8];
    #pragma unroll
    for (int i = 0; i < 8; i++)
        #pragma unroll
        for (int j = 0; j < 8; j++) acc[i][j] = 0.f;

    bool avalid = (bm + arow) < M;
    const float* Aptr = A + (size_t)(bm + arow) * K + acol;
    const float* Bptr = Bm + (size_t)brow * N + bn + bcol;

    for (int k0 = 0; k0 < K; k0 += 8) {
        float4 av = avalid ? *(const float4*)(Aptr + k0) : make_float4(0.f,0.f,0.f,0.f);
        As[acol+0][arow] = av.x; As[acol+1][arow] = av.y;
        As[acol+2][arow] = av.z; As[acol+3][arow] = av.w;
        *(float4*)&Bs[brow][bcol] = *(const float4*)(Bptr + (size_t)k0 * N);
        __syncthreads();
        #pragma unroll
        for (int k = 0; k < 8; k++) {
            float4 a0 = *(const float4*)&As[k][tr];
            float4 a1 = *(const float4*)&As[k][tr+4];
            float4 b0 = *(const float4*)&Bs[k][tc];
            float4 b1 = *(const float4*)&Bs[k][tc+4];
            float ra[8] = {a0.x,a0.y,a0.z,a0.w,a1.x,a1.y,a1.z,a1.w};
            float rb[8] = {b0.x,b0.y,b0.z,b0.w,b1.x,b1.y,b1.z,b1.w};
            #pragma unroll
            for (int i = 0; i < 8; i++)
                #pragma unroll
                for (int j = 0; j < 8; j++) acc[i][j] += ra[i]*rb[j];
        }
        __syncthreads();
    }
    #pragma unroll
    for (int i = 0; i < 8; i++) {
        int gr = bm + tr + i;
        if (gr >= M) break;
        #pragma unroll
        for (int j = 0; j < 8; j += 4) {
            int gc = bn + tc + j;
            float4 v = make_float4(acc[i][j],acc[i][j+1],acc[i][j+2],acc[i][j+3]);
            float4 bb = *(const float4*)&bias[gc];
            v.x += bb.x; v.y += bb.y; v.z += bb.z; v.w += bb.w;
            if (ACCUM) {
                float4 o = *(const float4*)&Cm[(size_t)gr*N + gc];
                v.x += o.x; v.y += o.y; v.z += o.z; v.w += o.w;
            }
            if (RELU) {
                v.x = fmaxf(v.x,0.f); v.y = fmaxf(v.y,0.f);
                v.z = fmaxf(v.z,0.f); v.w = fmaxf(v.w,0.f);
            }
            *(float4*)&Cm[(size_t)gr*N + gc] = v;
        }
    }
}

// ---------------- LayerNorm over C=512, one block per (l,b) row --------------------
__global__ void ln_kernel(const float* __restrict__ in, float* __restrict__ out,
    const float* __restrict__ w, const float* __restrict__ b,
    const float* __restrict__ pos, int rows)
{
    int row = blockIdx.x;
    const float* xr = in + (size_t)row * 512;
    int tid = threadIdx.x;  // 128
    float v[4]; float s = 0.f, s2 = 0.f;
    #pragma unroll
    for (int i = 0; i < 4; i++) {
        float t = xr[tid + 128*i]; v[i] = t; s += t; s2 += t*t;
    }
    #pragma unroll
    for (int o = 16; o; o >>= 1) {
        s  += __shfl_xor_sync(0xffffffffu, s,  o);
        s2 += __shfl_xor_sync(0xffffffffu, s2, o);
    }
    __shared__ float sh0[4], sh1[4];
    int wp = tid >> 5;
    if ((tid & 31) == 0) { sh0[wp] = s; sh1[wp] = s2; }
    __syncthreads();
    s  = sh0[0]+sh0[1]+sh0[2]+sh0[3];
    s2 = sh1[0]+sh1[1]+sh1[2]+sh1[3];
    float mean = s * (1.f/512.f);
    float var  = s2 * (1.f/512.f) - mean*mean;
    float rstd = rsqrtf(var + 1e-5f);
    int l = row >> 3;   // B = 8
    #pragma unroll
    for (int i = 0; i < 4; i++) {
        int c = tid + 128*i;
        float o = (v[i]-mean)*rstd*w[c] + b[c];
        if (pos) o += pos[(size_t)l*512 + c];
        out[(size_t)row*512 + c] = o;
    }
}

// ---------------- CLS attention: one block per (b,h), keys over all L --------------
__global__ void cls_attn(const float* __restrict__ qkv, float* __restrict__ att, int L)
{
    int b = blockIdx.x >> 3, h = blockIdx.x & 7;
    __shared__ float p[3137];
    __shared__ float qs[64];
    __shared__ float red[256];
    int tid = threadIdx.x;
    if (tid < 64) qs[tid] = qkv[(size_t)b*1536 + h*64 + tid] * 0.125f;
    __syncthreads();
    float lmax = -1e30f;
    for (int l = tid; l < L; l += 256) {
        const float4* kp = (const float4*)&qkv[((size_t)l*8 + b)*1536 + 512 + h*64];
        const float4* qq = (const float4*)qs;
        float s = 0.f;
        #pragma unroll
        for (int d = 0; d < 16; d++) {
            float4 a = qq[d], k4 = kp[d];
            s += a.x*k4.x + a.y*k4.y + a.z*k4.z + a.w*k4.w;
        }
        p[l] = s; lmax = fmaxf(lmax, s);
    }
    red[tid] = lmax; __syncthreads();
    for (int o = 128; o; o >>= 1) { if (tid < o) red[tid] = fmaxf(red[tid], red[tid+o]); __syncthreads(); }
    float gmax = red[0]; __syncthreads();
    float lsum = 0.f;
    for (int l = tid; l < L; l += 256) { float e = __expf(p[l]-gmax); p[l] = e; lsum += e; }
    red[tid] = lsum; __syncthreads();
    for (int o = 128; o; o >>= 1) { if (tid < o) red[tid] += red[tid+o]; __syncthreads(); }
    float inv = 1.f / red[0];
    __syncthreads();
    int d = tid & 63, g = tid >> 6;
    float acc = 0.f;
    for (int l = g; l < L; l += 4)
        acc += p[l] * qkv[((size_t)l*8 + b)*1536 + 1024 + h*64 + d];
    red[tid] = acc; __syncthreads();
    if (g == 0)
        att[(size_t)b*512 + h*64 + d] = (red[d]+red[64+d]+red[128+d]+red[192+d]) * inv;
}

// ---------------- temporal attention + std top-k pooling: block per (h,b,w) --------
__global__ void temporal_attn(const float* __restrict__ qkv, float* __restrict__ yout,
                              int* __restrict__ idxout, int t, int tp)
{
    int w = blockIdx.x % 196;
    int b = (blockIdx.x / 196) & 7;
    int h = blockIdx.x / (196*8);
    __shared__ float sq[16][64], sk[16][64], sv[16][64];
    __shared__ float sat[16][17];
    __shared__ float ssig[16];
    __shared__ int skeep[16], snew[16];
    int tid = threadIdx.x;  // 128
    for (int i = tid; i < t*64; i += 128) {
        int ti = i >> 6, d = i & 63;
        size_t base = ((size_t)(1 + ti*196 + w)*8 + b)*1536 + h*64 + d;
        sq[ti][d] = qkv[base] * 0.125f;
        sk[ti][d] = qkv[base + 512];
        sv[ti][d] = qkv[base + 1024];
    }
    __syncthreads();
    for (int i = tid; i < t*t; i += 128) {
        int qi = i / t, kj = i % t;
        float s = 0.f;
        #pragma unroll
        for (int d = 0; d < 64; d++) s += sq[qi][d]*sk[kj][d];
        sat[qi][kj] = s;
    }
    __syncthreads();
    if (tid < t) {
        float m = -1e30f;
        for (int j = 0; j < t; j++) m = fmaxf(m, sat[tid][j]);
        float s = 0.f;
        for (int j = 0; j < t; j++) { float e = expf(sat[tid][j]-m); sat[tid][j] = e; s += e; }
        float inv = 1.f / s;
        float mean = 0.f;
        for (int j = 0; j < t; j++) { float a = sat[tid][j]*inv; sat[tid][j] = a; mean += a; }
        mean /= (float)t;
        float var = 0.f;
        for (int j = 0; j < t; j++) { float d0 = sat[tid][j]-mean; var += d0*d0; }
        ssig[tid] = sqrtf(var / (float)(t-1));
    }
    __syncthreads();
    if (tid < t) {
        float si = ssig[tid]; int r = 0;
        for (int j = 0; j < t; j++)
            if (ssig[j] > si || (ssig[j] == si && j < tid)) r++;
        skeep[tid] = (r < tp) ? 1 : 0;
    }
    __syncthreads();
    if (tid == 0) {
        int c = 0;
        for (int i = 0; i < t; i++)
            if (skeep[i]) { snew[i] = c; idxout[((size_t)(h*8+b)*196 + w)*tp + c] = i; c++; }
    }
    __syncthreads();
    for (int i = tid; i < t*64; i += 128) {
        int qi = i >> 6, d = i & 63;
        if (!skeep[qi]) continue;
        float s = 0.f;
        for (int j = 0; j < t; j++) s += sat[qi][j]*sv[j][d];
        yout[((size_t)(1 + snew[qi]*196 + w)*8 + b)*512 + h*64 + d] = s;
    }
}

// ---------------- spatial attention: block per (h,b,ti); K,V in smem ----------------
__global__ __launch_bounds__(256) void spatial_attn(const float* __restrict__ qkvs,
    float* __restrict__ att, int tp)
{
    int ti = blockIdx.x % tp;
    int b  = (blockIdx.x / tp) & 7;
    int h  = blockIdx.x / (tp*8);
    extern __shared__ float sm[];
    float* Ks = sm;                 // 196*68
    float* Vs = Ks + 196*68;        // 196*68
    float* Ps = Vs + 196*68;        // 8*196
    float* Qs = Ps + 8*196;         // 8*64
    int tid = threadIdx.x, lane = tid & 31, warp = tid >> 5;
    for (int i = tid; i < 196*64; i += 256) {
        int w = i >> 6, d = i & 63;
        size_t base = ((size_t)(ti*196 + w)*8 + b)*1536 + h*64 + d;
        Ks[w*68 + d] = qkvs[base + 512];
        Vs[w*68 + d] = qkvs[base + 1024];
    }
    __syncthreads();
    for (int wq = warp; wq < 196; wq += 8) {
        size_t qbase = ((size_t)(ti*196 + wq)*8 + b)*1536 + h*64;
        Qs[warp*64 + lane]      = qkvs[qbase + lane]      * 0.125f;
        Qs[warp*64 + lane + 32] = qkvs[qbase + lane + 32] * 0.125f;
        __syncwarp();
        float m = -1e30f;
        float sc[7];
        int nidx = 0;
        for (int kk = lane; kk < 196; kk += 32, nidx++) {
            const float4* qv = (const float4*)(Qs + warp*64);
            const float4* kr = (const float4*)(Ks + kk*68);
            float s = 0.f;
            #pragma unroll
            for (int d4 = 0; d4 < 16; d4++) {
                float4 a = qv[d4], k4 = kr[d4];
                s += a.x*k4.x + a.y*k4.y + a.z*k4.z + a.w*k4.w;
            }
            sc[nidx] = s; m = fmaxf(m, s);
        }
        #pragma unroll
        for (int o = 16; o; o >>= 1) m = fmaxf(m, __shfl_xor_sync(0xffffffffu, m, o));
        float sum = 0.f; nidx = 0;
        for (int kk = lane; kk < 196; kk += 32, nidx++) {
            float e = __expf(sc[nidx]-m);
            Ps[warp*196 + kk] = e; sum += e;
        }
        #pragma unroll
        for (int o = 16; o; o >>= 1) sum += __shfl_xor_sync(0xffffffffu, sum, o);
        float inv = 1.f / sum;
        __syncwarp();
        float a0 = 0.f, a1 = 0.f;
        for (int kk = 0; kk < 196; kk++) {
            float pv = Ps[warp*196 + kk];
            float2 vv = *(const float2*)(Vs + kk*68 + 2*lane);
            a0 += pv*vv.x; a1 += pv*vv.y;
        }
        size_t obase = ((size_t)(1 + ti*196 + wq)*8 + b)*512 + h*64 + 2*lane;
        att[obase]   = a0*inv;
        att[obase+1] = a1*inv;
        __syncwarp();
    }
}

// ---------------- residual pooling gather ------------------------------------------
__global__ void pool_gather(const float* __restrict__ x, float* __restrict__ xn,
    const int* __restrict__ idx, int tp)
{
    int total = (1 + tp*196)*8*512;
    for (int e = blockIdx.x*blockDim.x + threadIdx.x; e < total; e += gridDim.x*blockDim.x) {
        if (e < 8*512) { xn[e] = x[e]; continue; }
        int c = e & 511;
        int row = e >> 9;
        int b = row & 7;
        int l = row >> 3;
        int lt = l - 1;
        int nt = lt / 196, w = lt % 196;
        int h = c >> 6;
        int st = idx[((size_t)(h*8 + b)*196 + w)*tp + nt];
        xn[e] = x[(((size_t)(1 + st*196 + w)*8 + b) << 9) + c];
    }
}

// ---------------- patch embed helpers ----------------------------------------------
__global__ void im2col_k(const float* __restrict__ src, float* __restrict__ out)
{
    int idx = blockIdx.x*256 + threadIdx.x;
    if (idx >= 25088*768) return;
    int m = idx / 768, k = idx - m*768;
    int b = m & 7; int sp = m >> 3;
    int ti = sp / 196; int p = sp % 196;
    int ph = p / 14, pw = p % 14;
    int ci = k >> 8; int r = k & 255; int kh = r >> 4, kw = r & 15;
    out[idx] = src[(((size_t)(b*3 + ci)*16 + ti)*224 + (ph*16 + kh))*224 + (pw*16 + kw)];
}

__global__ void transpose_w(const float* __restrict__ w, float* __restrict__ wt)
{
    int idx = blockIdx.x*256 + threadIdx.x;
    if (idx >= 768*512) return;
    int k = idx / 512, co = idx - k*512;
    wt[idx] = w[(size_t)co*768 + k];
}

__global__ void cls_fill(const float* __restrict__ cls, float* __restrict__ x)
{
    int idx = blockIdx.x*256 + threadIdx.x;
    if (idx < 8*512) x[idx] = cls[idx & 511];
}

// ---------------- final LN (row 0 only) + classifier --------------------------------
__global__ void final_fc(const float* __restrict__ x, const float* __restrict__ enw,
    const float* __restrict__ enb, const float* __restrict__ fcw,
    const float* __restrict__ fcb, float* __restrict__ out, int ncls)
{
    int b = blockIdx.x; int tid = threadIdx.x;   // 256
    __shared__ float xn[512];
    __shared__ float sh0[8], sh1[8];
    float v0 = x[(size_t)b*512 + tid];
    float v1 = x[(size_t)b*512 + tid + 256];
    float s = v0 + v1, s2 = v0*v0 + v1*v1;
    #pragma unroll
    for (int o = 16; o; o >>= 1) {
        s  += __shfl_xor_sync(0xffffffffu, s,  o);
        s2 += __shfl_xor_sync(0xffffffffu, s2, o);
    }
    int wp = tid >> 5;
    if ((tid & 31) == 0) { sh0[wp] = s; sh1[wp] = s2; }
    __syncthreads();
    if (tid == 0) {
        float S = 0.f, S2 = 0.f;
        for (int i = 0; i < 8; i++) { S += sh0[i]; S2 += sh1[i]; }
        sh0[0] = S; sh1[0] = S2;
    }
    __syncthreads();
    float mean = sh0[0]*(1.f/512.f);
    float var  = sh1[0]*(1.f/512.f) - mean*mean;
    float rstd = rsqrtf(var + 1e-5f);
    xn[tid]     = (v0-mean)*rstd*enw[tid]     + enb[tid];
    xn[tid+256] = (v1-mean)*rstd*enw[tid+256] + enb[tid+256];
    __syncthreads();
    for (int n = tid; n < ncls; n += 256) {
        float s3 = fcb[n];
        for (int c = 0; c < 512; c++) s3 += xn[c]*fcw[(size_t)c*ncls + n];
        out[(size_t)b*ncls + n] = s3;
    }
}

// ---------------- host orchestration ------------------------------------------------
static void launch_gemm(const float* A, const float* Bm, const float* bias, float* Cc,
                        int M, int N, int K, bool accum, bool relu)
{
    dim3 g(N/128, CDIV(M,128));
    if (accum)      sgemm<true ,false><<<g,256>>>(A,Bm,bias,Cc,M,N,K);
    else if (relu)  sgemm<false,true ><<<g,256>>>(A,Bm,bias,Cc,M,N,K);
    else            sgemm<false,false><<<g,256>>>(A,Bm,bias,Cc,M,N,K);
}

extern "C" void kernel_launch(void* const* d_in, const int* in_sizes, int n_in,
                              void* d_out, int out_size)
{
    const float* src   = (const float*)d_in[0];
    const float* convw = (const float*)d_in[1];
    const float* convb = (const float*)d_in[2];
    const float* cls   = (const float*)d_in[3];
    const float* pos   = (const float*)d_in[4];
    const float* Wt    = (const float*)d_in[5];
    const float* bt    = (const float*)d_in[6];
    const float* Ws    = (const float*)d_in[7];
    const float* bs    = (const float*)d_in[8];
    const float* Wo    = (const float*)d_in[9];
    const float* bo    = (const float*)d_in[10];
    const float* n1w   = (const float*)d_in[11];
    const float* n1b   = (const float*)d_in[12];
    const float* n2w   = (const float*)d_in[13];
    const float* n2b   = (const float*)d_in[14];
    const float* W1    = (const float*)d_in[15];
    const float* b1    = (const float*)d_in[16];
    const float* W2    = (const float*)d_in[17];
    const float* b2    = (const float*)d_in[18];
    const float* enw   = (const float*)d_in[19];
    const float* enb   = (const float*)d_in[20];
    const float* fcw   = (const float*)d_in[21];
    const float* fcb   = (const float*)d_in[22];
    float* outp = (float*)d_out;
    int ncls = in_sizes[22];

    void* p;
    cudaGetSymbolAddress(&p, g_xA);  float* xA   = (float*)p;
    cudaGetSymbolAddress(&p, g_xB);  float* xB   = (float*)p;
    cudaGetSymbolAddress(&p, g_ln);  float* lnb  = (float*)p;
    cudaGetSymbolAddress(&p, g_att); float* attb = (float*)p;
    cudaGetSymbolAddress(&p, g_qkv); float* qkvb = (float*)p;
    cudaGetSymbolAddress(&p, g_h);   float* hb   = (float*)p;
    cudaGetSymbolAddress(&p, g_wT);  float* wT   = (float*)p;
    cudaGetSymbolAddress(&p, g_idx); int*   idxb = (int*)p;

    cudaFuncSetAttribute(spatial_attn, cudaFuncAttributeMaxDynamicSharedMemorySize, SPAT_SMEM);

    // ---- patch embed: conv as im2col + GEMM ----
    transpose_w<<<CDIV(768*512,256),256>>>(convw, wT);
    im2col_k<<<CDIV(25088*768,256),256>>>(src, hb);
    launch_gemm(hb, wT, convb, xA + 8*512, 25088, 512, 768, false, false);
    cls_fill<<<CDIV(8*512,256),256>>>(cls, xA);

    float* x  = xA;
    float* xo = xB;
    int t = 16;
    for (int i = 0; i < 6; i++) {
        int pk = (i == 1 || i == 3 || i == 5) ? 2 : 0;
        int tp = t - pk;
        int L = t*196 + 1, M = L*8;

        // LN1 (+pos for layer 0)
        ln_kernel<<<M,128>>>(x, lnb, n1w + i*512, n1b + i*512, (i == 0) ? pos : nullptr, M);
        // QKV
        launch_gemm(lnb, Wt + (size_t)i*512*1536, bt + (size_t)i*1536, qkvb, M, 1536, 512, false, false);
        // CLS attention -> att row 0
        cls_attn<<<64,256>>>(qkvb, attb, L);
        // temporal attention (+pool selection) -> att rows 1..tp*196
        temporal_attn<<<8*8*196,128>>>(qkvb, attb, idxb, t, tp);
        // spatial QKV (reuse qkv buffer as output)
        int Ms = tp*196*8;
        launch_gemm(attb + 8*512, Ws + (size_t)i*512*1536, bs + (size_t)i*1536, qkvb, Ms, 1536, 512, false, false);
        // spatial attention -> att rows 1..tp*196 (in place over its GEMM input rows)
        spatial_attn<<<64*tp,256,SPAT_SMEM>>>(qkvb, attb, tp);

        int Lp = tp*196 + 1, Mp = Lp*8;
        float* xr = x;
        if (pk > 0) {
            pool_gather<<<CDIV(Mp*512,256),256>>>(x, xo, idxb, tp);
            xr = xo;
        }
        // x = pooled_residual + att @ Wo + bo   (GEMM accumulates into residual)
        launch_gemm(attb, Wo + (size_t)i*512*512, bo + (size_t)i*512, xr, Mp, 512, 512, true, false);
        if (pk > 0) { xo = x; x = xr; }
        t = tp;

        // MLP: x += relu(LN2(x) @ W1 + b1) @ W2 + b2
        ln_kernel<<<Mp,128>>>(x, lnb, n2w + i*512, n2b + i*512, nullptr, Mp);
        launch_gemm(lnb, W1 + (size_t)i*512*2048, b1 + (size_t)i*2048, hb, Mp, 2048, 512, false, true);
        launch_gemm(hb,  W2 + (size_t)i*2048*512, b2 + (size_t)i*512,  x,  Mp,  512, 2048, true, false);
    }

    final_fc<<<8,256>>>(x, enw, enb, fcw, fcb, outp, ncls);
}

// round 4
// speedup vs baseline: 1.0409x; 1.0409x over previous
#include <cuda_runtime.h>
#include <cstdint>
#include <math.h>

#define CDIV(a,b) (((a)+(b)-1)/(b))

typedef unsigned long long ull;

// ---- packed fp32x2 helpers (Blackwell FFMA2 path; exact fp32 semantics) ----
__device__ __forceinline__ void fma2(ull& d, ull a, ull b) {
    asm("fma.rn.f32x2 %0, %1, %2, %0;" : "+l"(d) : "l"(a), "l"(b));
}
__device__ __forceinline__ ull splat2(float x) {
    ull r; unsigned u = __float_as_uint(x);
    asm("mov.b64 %0, {%1, %1};" : "=l"(r) : "r"(u));
    return r;
}
__device__ __forceinline__ float2 unpack2(ull v) {
    unsigned lo, hi;
    asm("mov.b64 {%0, %1}, %2;" : "=r"(lo), "=r"(hi) : "l"(v));
    return make_float2(__uint_as_float(lo), __uint_as_float(hi));
}
__device__ __forceinline__ ull d2u(double d) { return __double_as_longlong(d); }

// ---------------- scratch (static device globals; no runtime alloc) ----------------
__device__ float g_xA [3137*8*512];
__device__ float g_xB [3137*8*512];
__device__ float g_ln [3137*8*512];
__device__ float g_att[3137*8*512];
__device__ float g_qkv[3137*8*1536];
__device__ float g_h  [3137*8*2048];   // also im2col scratch (needs 25088*768 < size)
__device__ int   g_idx[8*8*196*16];
__device__ float g_wT [768*512];

static const int SPAT_SMEM = (2*196*68 + 8*196 + 8*64) * 4;  // 114944 B

// ---------------- SGEMM: C[M,N] = A[M,K] @ B[K,N] + bias (+C if ACCUM) (ReLU opt) ----
// A row-major MxK, B row-major KxN, C row-major MxN. N % 128 == 0, K % 8 == 0.
// Inner loop uses packed fma.rn.f32x2 (2 exact fp32 FMA per issue slot) and
// software-pipelined global loads.
template<bool ACCUM, bool RELU>
__global__ __launch_bounds__(256) void sgemm(const float* __restrict__ A,
    const float* __restrict__ Bm, const float* __restrict__ bias,
    float* __restrict__ Cm, int M, int N, int K)
{
    __shared__ float As[8][128];
    __shared__ float Bs[8][128];
    int tid = threadIdx.x;
    int bm = blockIdx.y * 128, bn = blockIdx.x * 128;
    int tr = (tid >> 4) << 3;       // 0..120
    int tc = (tid & 15) << 3;       // 0..120
    int arow = tid >> 1, acol = (tid & 1) << 2;
    int brow = tid >> 5, bcol = (tid & 31) << 2;

    ull acc2[8][4];
    #pragma unroll
    for (int i = 0; i < 8; i++)
        #pragma unroll
        for (int j = 0; j < 4; j++) acc2[i][j] = 0ull;   // two packed +0.0f

    bool avalid = (bm + arow) < M;
    const float* Aptr = A + (size_t)(bm + arow) * K + acol;
    const float* Bptr = Bm + (size_t)brow * N + bn + bcol;

    float4 av = avalid ? *(const float4*)(Aptr) : make_float4(0.f,0.f,0.f,0.f);
    float4 bv = *(const float4*)(Bptr);

    for (int k0 = 0; k0 < K; k0 += 8) {
        As[acol+0][arow] = av.x; As[acol+1][arow] = av.y;
        As[acol+2][arow] = av.z; As[acol+3][arow] = av.w;
        *(float4*)&Bs[brow][bcol] = bv;
        __syncthreads();
        if (k0 + 8 < K) {   // prefetch next tile under compute
            av = avalid ? *(const float4*)(Aptr + k0 + 8) : make_float4(0.f,0.f,0.f,0.f);
            bv = *(const float4*)(Bptr + (size_t)(k0 + 8) * N);
        }
        #pragma unroll
        for (int k = 0; k < 8; k++) {
            float4 a0 = *(const float4*)&As[k][tr];
            float4 a1 = *(const float4*)&As[k][tr+4];
            double2 bd0 = *(const double2*)&Bs[k][tc];
            double2 bd1 = *(const double2*)&Bs[k][tc+4];
            ull b2[4] = { d2u(bd0.x), d2u(bd0.y), d2u(bd1.x), d2u(bd1.y) };
            float ra[8] = {a0.x,a0.y,a0.z,a0.w,a1.x,a1.y,a1.z,a1.w};
            #pragma unroll
            for (int i = 0; i < 8; i++) {
                ull a2 = splat2(ra[i]);
                #pragma unroll
                for (int jp = 0; jp < 4; jp++) fma2(acc2[i][jp], a2, b2[jp]);
            }
        }
        __syncthreads();
    }
    #pragma unroll
    for (int i = 0; i < 8; i++) {
        int gr = bm + tr + i;
        if (gr >= M) break;
        #pragma unroll
        for (int jh = 0; jh < 2; jh++) {
            int gc = bn + tc + jh*4;
            float2 p0 = unpack2(acc2[i][jh*2 + 0]);
            float2 p1 = unpack2(acc2[i][jh*2 + 1]);
            float4 v = make_float4(p0.x, p0.y, p1.x, p1.y);
            float4 bb = *(const float4*)&bias[gc];
            v.x += bb.x; v.y += bb.y; v.z += bb.z; v.w += bb.w;
            if (ACCUM) {
                float4 o = *(const float4*)&Cm[(size_t)gr*N + gc];
                v.x += o.x; v.y += o.y; v.z += o.z; v.w += o.w;
            }
            if (RELU) {
                v.x = fmaxf(v.x,0.f); v.y = fmaxf(v.y,0.f);
                v.z = fmaxf(v.z,0.f); v.w = fmaxf(v.w,0.f);
            }
            *(float4*)&Cm[(size_t)gr*N + gc] = v;
        }
    }
}

// ---------------- LayerNorm over C=512, one block per (l,b) row --------------------
__global__ void ln_kernel(const float* __restrict__ in, float* __restrict__ out,
    const float* __restrict__ w, const float* __restrict__ b,
    const float* __restrict__ pos, int rows)
{
    int row = blockIdx.x;
    const float* xr = in + (size_t)row * 512;
    int tid = threadIdx.x;  // 128
    float v[4]; float s = 0.f, s2 = 0.f;
    #pragma unroll
    for (int i = 0; i < 4; i++) {
        float t = xr[tid + 128*i]; v[i] = t; s += t; s2 += t*t;
    }
    #pragma unroll
    for (int o = 16; o; o >>= 1) {
        s  += __shfl_xor_sync(0xffffffffu, s,  o);
        s2 += __shfl_xor_sync(0xffffffffu, s2, o);
    }
    __shared__ float sh0[4], sh1[4];
    int wp = tid >> 5;
    if ((tid & 31) == 0) { sh0[wp] = s; sh1[wp] = s2; }
    __syncthreads();
    s  = sh0[0]+sh0[1]+sh0[2]+sh0[3];
    s2 = sh1[0]+sh1[1]+sh1[2]+sh1[3];
    float mean = s * (1.f/512.f);
    float var  = s2 * (1.f/512.f) - mean*mean;
    float rstd = rsqrtf(var + 1e-5f);
    int l = row >> 3;   // B = 8
    #pragma unroll
    for (int i = 0; i < 4; i++) {
        int c = tid + 128*i;
        float o = (v[i]-mean)*rstd*w[c] + b[c];
        if (pos) o += pos[(size_t)l*512 + c];
        out[(size_t)row*512 + c] = o;
    }
}

// ---------------- CLS attention: one block per (b,h), keys over all L --------------
__global__ void cls_attn(const float* __restrict__ qkv, float* __restrict__ att, int L)
{
    int b = blockIdx.x >> 3, h = blockIdx.x & 7;
    __shared__ float p[3137];
    __shared__ float qs[64];
    __shared__ float red[256];
    int tid = threadIdx.x;
    if (tid < 64) qs[tid] = qkv[(size_t)b*1536 + h*64 + tid] * 0.125f;
    __syncthreads();
    float lmax = -1e30f;
    for (int l = tid; l < L; l += 256) {
        const float4* kp = (const float4*)&qkv[((size_t)l*8 + b)*1536 + 512 + h*64];
        const float4* qq = (const float4*)qs;
        float s = 0.f;
        #pragma unroll
        for (int d = 0; d < 16; d++) {
            float4 a = qq[d], k4 = kp[d];
            s += a.x*k4.x + a.y*k4.y + a.z*k4.z + a.w*k4.w;
        }
        p[l] = s; lmax = fmaxf(lmax, s);
    }
    red[tid] = lmax; __syncthreads();
    for (int o = 128; o; o >>= 1) { if (tid < o) red[tid] = fmaxf(red[tid], red[tid+o]); __syncthreads(); }
    float gmax = red[0]; __syncthreads();
    float lsum = 0.f;
    for (int l = tid; l < L; l += 256) { float e = __expf(p[l]-gmax); p[l] = e; lsum += e; }
    red[tid] = lsum; __syncthreads();
    for (int o = 128; o; o >>= 1) { if (tid < o) red[tid] += red[tid+o]; __syncthreads(); }
    float inv = 1.f / red[0];
    __syncthreads();
    int d = tid & 63, g = tid >> 6;
    float acc = 0.f;
    for (int l = g; l < L; l += 4)
        acc += p[l] * qkv[((size_t)l*8 + b)*1536 + 1024 + h*64 + d];
    red[tid] = acc; __syncthreads();
    if (g == 0)
        att[(size_t)b*512 + h*64 + d] = (red[d]+red[64+d]+red[128+d]+red[192+d]) * inv;
}

// ---------------- temporal attention + std top-k pooling: block per (h,b,w) --------
__global__ void temporal_attn(const float* __restrict__ qkv, float* __restrict__ yout,
                              int* __restrict__ idxout, int t, int tp)
{
    int w = blockIdx.x % 196;
    int b = (blockIdx.x / 196) & 7;
    int h = blockIdx.x / (196*8);
    __shared__ float sq[16][64], sk[16][64], sv[16][64];
    __shared__ float sat[16][17];
    __shared__ float ssig[16];
    __shared__ int skeep[16], snew[16];
    int tid = threadIdx.x;  // 128
    for (int i = tid; i < t*64; i += 128) {
        int ti = i >> 6, d = i & 63;
        size_t base = ((size_t)(1 + ti*196 + w)*8 + b)*1536 + h*64 + d;
        sq[ti][d] = qkv[base] * 0.125f;
        sk[ti][d] = qkv[base + 512];
        sv[ti][d] = qkv[base + 1024];
    }
    __syncthreads();
    for (int i = tid; i < t*t; i += 128) {
        int qi = i / t, kj = i % t;
        const double2* qd = (const double2*)sq[qi];
        const double2* kd = (const double2*)sk[kj];
        ull s2 = 0ull;
        #pragma unroll
        for (int d2 = 0; d2 < 16; d2++) {
            double2 qv = qd[d2], kv = kd[d2];
            fma2(s2, d2u(qv.x), d2u(kv.x));
            fma2(s2, d2u(qv.y), d2u(kv.y));
        }
        float2 sf = unpack2(s2);
        sat[qi][kj] = sf.x + sf.y;
    }
    __syncthreads();
    if (tid < t) {
        float m = -1e30f;
        for (int j = 0; j < t; j++) m = fmaxf(m, sat[tid][j]);
        float s = 0.f;
        for (int j = 0; j < t; j++) { float e = expf(sat[tid][j]-m); sat[tid][j] = e; s += e; }
        float inv = 1.f / s;
        float mean = 0.f;
        for (int j = 0; j < t; j++) { float a = sat[tid][j]*inv; sat[tid][j] = a; mean += a; }
        mean /= (float)t;
        float var = 0.f;
        for (int j = 0; j < t; j++) { float d0 = sat[tid][j]-mean; var += d0*d0; }
        ssig[tid] = sqrtf(var / (float)(t-1));
    }
    __syncthreads();
    if (tid < t) {
        float si = ssig[tid]; int r = 0;
        for (int j = 0; j < t; j++)
            if (ssig[j] > si || (ssig[j] == si && j < tid)) r++;
        skeep[tid] = (r < tp) ? 1 : 0;
    }
    __syncthreads();
    if (tid == 0) {
        int c = 0;
        for (int i = 0; i < t; i++)
            if (skeep[i]) { snew[i] = c; idxout[((size_t)(h*8+b)*196 + w)*tp + c] = i; c++; }
    }
    __syncthreads();
    for (int i = tid; i < t*64; i += 128) {
        int qi = i >> 6, d = i & 63;
        if (!skeep[qi]) continue;
        float s = 0.f;
        for (int j = 0; j < t; j++) s += sat[qi][j]*sv[j][d];
        yout[((size_t)(1 + snew[qi]*196 + w)*8 + b)*512 + h*64 + d] = s;
    }
}

// ---------------- spatial attention: block per (h,b,ti); K,V in smem ----------------
__global__ __launch_bounds__(256) void spatial_attn(const float* __restrict__ qkvs,
    float* __restrict__ att, int tp)
{
    int ti = blockIdx.x % tp;
    int b  = (blockIdx.x / tp) & 7;
    int h  = blockIdx.x / (tp*8);
    extern __shared__ float sm[];
    float* Ks = sm;                 // 196*68
    float* Vs = Ks + 196*68;        // 196*68
    float* Ps = Vs + 196*68;        // 8*196
    float* Qs = Ps + 8*196;         // 8*64
    int tid = threadIdx.x, lane = tid & 31, warp = tid >> 5;
    for (int i = tid; i < 196*64; i += 256) {
        int w = i >> 6, d = i & 63;
        size_t base = ((size_t)(ti*196 + w)*8 + b)*1536 + h*64 + d;
        Ks[w*68 + d] = qkvs[base + 512];
        Vs[w*68 + d] = qkvs[base + 1024];
    }
    __syncthreads();
    for (int wq = warp; wq < 196; wq += 8) {
        size_t qbase = ((size_t)(ti*196 + wq)*8 + b)*1536 + h*64;
        Qs[warp*64 + lane]      = qkvs[qbase + lane]      * 0.125f;
        Qs[warp*64 + lane + 32] = qkvs[qbase + lane + 32] * 0.125f;
        __syncwarp();
        // hoist packed Q into registers (reused over all 196 keys)
        ull q2[32];
        {
            const double2* qd = (const double2*)(Qs + warp*64);
            #pragma unroll
            for (int i = 0; i < 16; i++) {
                double2 qv = qd[i];
                q2[2*i]   = d2u(qv.x);
                q2[2*i+1] = d2u(qv.y);
            }
        }
        float m = -1e30f;
        float sc[7];
        int nidx = 0;
        for (int kk = lane; kk < 196; kk += 32, nidx++) {
            const double2* kd = (const double2*)(Ks + kk*68);
            ull s2 = 0ull;
            #pragma unroll
            for (int i = 0; i < 16; i++) {
                double2 kv = kd[i];
                fma2(s2, q2[2*i],   d2u(kv.x));
                fma2(s2, q2[2*i+1], d2u(kv.y));
            }
            float2 sf = unpack2(s2);
            float s = sf.x + sf.y;
            sc[nidx] = s; m = fmaxf(m, s);
        }
        #pragma unroll
        for (int o = 16; o; o >>= 1) m = fmaxf(m, __shfl_xor_sync(0xffffffffu, m, o));
        float sum = 0.f; nidx = 0;
        for (int kk = lane; kk < 196; kk += 32, nidx++) {
            float e = __expf(sc[nidx]-m);
            Ps[warp*196 + kk] = e; sum += e;
        }
        #pragma unroll
        for (int o = 16; o; o >>= 1) sum += __shfl_xor_sync(0xffffffffu, sum, o);
        float inv = 1.f / sum;
        __syncwarp();
        ull o2 = 0ull;
        for (int kk = 0; kk < 196; kk++) {
            float pv = Ps[warp*196 + kk];
            ull v2 = *(const ull*)(Vs + kk*68 + 2*lane);
            fma2(o2, splat2(pv), v2);
        }
        float2 of = unpack2(o2);
        size_t obase = ((size_t)(1 + ti*196 + wq)*8 + b)*512 + h*64 + 2*lane;
        *(float2*)&att[obase] = make_float2(of.x*inv, of.y*inv);
        __syncwarp();
    }
}

// ---------------- residual pooling gather ------------------------------------------
__global__ void pool_gather(const float* __restrict__ x, float* __restrict__ xn,
    const int* __restrict__ idx, int tp)
{
    int total = (1 + tp*196)*8*512;
    for (int e = blockIdx.x*blockDim.x + threadIdx.x; e < total; e += gridDim.x*blockDim.x) {
        if (e < 8*512) { xn[e] = x[e]; continue; }
        int c = e & 511;
        int row = e >> 9;
        int b = row & 7;
        int l = row >> 3;
        int lt = l - 1;
        int nt = lt / 196, w = lt % 196;
        int h = c >> 6;
        int st = idx[((size_t)(h*8 + b)*196 + w)*tp + nt];
        xn[e] = x[(((size_t)(1 + st*196 + w)*8 + b) << 9) + c];
    }
}

// ---------------- patch embed helpers ----------------------------------------------
__global__ void im2col_k(const float* __restrict__ src, float* __restrict__ out)
{
    int idx = blockIdx.x*256 + threadIdx.x;
    if (idx >= 25088*768) return;
    int m = idx / 768, k = idx - m*768;
    int b = m & 7; int sp = m >> 3;
    int ti = sp / 196; int p = sp % 196;
    int ph = p / 14, pw = p % 14;
    int ci = k >> 8; int r = k & 255; int kh = r >> 4, kw = r & 15;
    out[idx] = src[(((size_t)(b*3 + ci)*16 + ti)*224 + (ph*16 + kh))*224 + (pw*16 + kw)];
}

__global__ void transpose_w(const float* __restrict__ w, float* __restrict__ wt)
{
    int idx = blockIdx.x*256 + threadIdx.x;
    if (idx >= 768*512) return;
    int k = idx / 512, co = idx - k*512;
    wt[idx] = w[(size_t)co*768 + k];
}

__global__ void cls_fill(const float* __restrict__ cls, float* __restrict__ x)
{
    int idx = blockIdx.x*256 + threadIdx.x;
    if (idx < 8*512) x[idx] = cls[idx & 511];
}

// ---------------- final LN (row 0 only) + classifier --------------------------------
__global__ void final_fc(const float* __restrict__ x, const float* __restrict__ enw,
    const float* __restrict__ enb, const float* __restrict__ fcw,
    const float* __restrict__ fcb, float* __restrict__ out, int ncls)
{
    int b = blockIdx.x; int tid = threadIdx.x;   // 256
    __shared__ float xn[512];
    __shared__ float sh0[8], sh1[8];
    float v0 = x[(size_t)b*512 + tid];
    float v1 = x[(size_t)b*512 + tid + 256];
    float s = v0 + v1, s2 = v0*v0 + v1*v1;
    #pragma unroll
    for (int o = 16; o; o >>= 1) {
        s  += __shfl_xor_sync(0xffffffffu, s,  o);
        s2 += __shfl_xor_sync(0xffffffffu, s2, o);
    }
    int wp = tid >> 5;
    if ((tid & 31) == 0) { sh0[wp] = s; sh1[wp] = s2; }
    __syncthreads();
    if (tid == 0) {
        float S = 0.f, S2 = 0.f;
        for (int i = 0; i < 8; i++) { S += sh0[i]; S2 += sh1[i]; }
        sh0[0] = S; sh1[0] = S2;
    }
    __syncthreads();
    float mean = sh0[0]*(1.f/512.f);
    float var  = sh1[0]*(1.f/512.f) - mean*mean;
    float rstd = rsqrtf(var + 1e-5f);
    xn[tid]     = (v0-mean)*rstd*enw[tid]     + enb[tid];
    xn[tid+256] = (v1-mean)*rstd*enw[tid+256] + enb[tid+256];
    __syncthreads();
    for (int n = tid; n < ncls; n += 256) {
        float s3 = fcb[n];
        for (int c = 0; c < 512; c++) s3 += xn[c]*fcw[(size_t)c*ncls + n];
        out[(size_t)b*ncls + n] = s3;
    }
}

// ---------------- host orchestration ------------------------------------------------
static void launch_gemm(const float* A, const float* Bm, const float* bias, float* Cc,
                        int M, int N, int K, bool accum, bool relu)
{
    dim3 g(N/128, CDIV(M,128));
    if (accum)      sgemm<true ,false><<<g,256>>>(A,Bm,bias,Cc,M,N,K);
    else if (relu)  sgemm<false,true ><<<g,256>>>(A,Bm,bias,Cc,M,N,K);
    else            sgemm<false,false><<<g,256>>>(A,Bm,bias,Cc,M,N,K);
}

extern "C" void kernel_launch(void* const* d_in, const int* in_sizes, int n_in,
                              void* d_out, int out_size)
{
    const float* src   = (const float*)d_in[0];
    const float* convw = (const float*)d_in[1];
    const float* convb = (const float*)d_in[2];
    const float* cls   = (const float*)d_in[3];
    const float* pos   = (const float*)d_in[4];
    const float* Wt    = (const float*)d_in[5];
    const float* bt    = (const float*)d_in[6];
    const float* Ws    = (const float*)d_in[7];
    const float* bs    = (const float*)d_in[8];
    const float* Wo    = (const float*)d_in[9];
    const float* bo    = (const float*)d_in[10];
    const float* n1w   = (const float*)d_in[11];
    const float* n1b   = (const float*)d_in[12];
    const float* n2w   = (const float*)d_in[13];
    const float* n2b   = (const float*)d_in[14];
    const float* W1    = (const float*)d_in[15];
    const float* b1    = (const float*)d_in[16];
    const float* W2    = (const float*)d_in[17];
    const float* b2    = (const float*)d_in[18];
    const float* enw   = (const float*)d_in[19];
    const float* enb   = (const float*)d_in[20];
    const float* fcw   = (const float*)d_in[21];
    const float* fcb   = (const float*)d_in[22];
    float* outp = (float*)d_out;
    int ncls = in_sizes[22];

    void* p;
    cudaGetSymbolAddress(&p, g_xA);  float* xA   = (float*)p;
    cudaGetSymbolAddress(&p, g_xB);  float* xB   = (float*)p;
    cudaGetSymbolAddress(&p, g_ln);  float* lnb  = (float*)p;
    cudaGetSymbolAddress(&p, g_att); float* attb = (float*)p;
    cudaGetSymbolAddress(&p, g_qkv); float* qkvb = (float*)p;
    cudaGetSymbolAddress(&p, g_h);   float* hb   = (float*)p;
    cudaGetSymbolAddress(&p, g_wT);  float* wT   = (float*)p;
    cudaGetSymbolAddress(&p, g_idx); int*   idxb = (int*)p;

    cudaFuncSetAttribute(spatial_attn, cudaFuncAttributeMaxDynamicSharedMemorySize, SPAT_SMEM);

    // ---- patch embed: conv as im2col + GEMM ----
    transpose_w<<<CDIV(768*512,256),256>>>(convw, wT);
    im2col_k<<<CDIV(25088*768,256),256>>>(src, hb);
    launch_gemm(hb, wT, convb, xA + 8*512, 25088, 512, 768, false, false);
    cls_fill<<<CDIV(8*512,256),256>>>(cls, xA);

    float* x  = xA;
    float* xo = xB;
    int t = 16;
    for (int i = 0; i < 6; i++) {
        int pk = (i == 1 || i == 3 || i == 5) ? 2 : 0;
        int tp = t - pk;
        int L = t*196 + 1, M = L*8;

        // LN1 (+pos for layer 0)
        ln_kernel<<<M,128>>>(x, lnb, n1w + i*512, n1b + i*512, (i == 0) ? pos : nullptr, M);
        // QKV
        launch_gemm(lnb, Wt + (size_t)i*512*1536, bt + (size_t)i*1536, qkvb, M, 1536, 512, false, false);
        // CLS attention -> att row 0
        cls_attn<<<64,256>>>(qkvb, attb, L);
        // temporal attention (+pool selection) -> att rows 1..tp*196
        temporal_attn<<<8*8*196,128>>>(qkvb, attb, idxb, t, tp);
        // spatial QKV (reuse qkv buffer as output)
        int Ms = tp*196*8;
        launch_gemm(attb + 8*512, Ws + (size_t)i*512*1536, bs + (size_t)i*1536, qkvb, Ms, 1536, 512, false, false);
        // spatial attention -> att rows 1..tp*196 (in place over its GEMM input rows)
        spatial_attn<<<64*tp,256,SPAT_SMEM>>>(qkvb, attb, tp);

        int Lp = tp*196 + 1, Mp = Lp*8;
        float* xr = x;
        if (pk > 0) {
            pool_gather<<<CDIV(Mp*512,256),256>>>(x, xo, idxb, tp);
            xr = xo;
        }
        // x = pooled_residual + att @ Wo + bo   (GEMM accumulates into residual)
        launch_gemm(attb, Wo + (size_t)i*512*512, bo + (size_t)i*512, xr, Mp, 512, 512, true, false);
        if (pk > 0) { xo = x; x = xr; }
        t = tp;

        // MLP: x += relu(LN2(x) @ W1 + b1) @ W2 + b2
        ln_kernel<<<Mp,128>>>(x, lnb, n2w + i*512, n2b + i*512, nullptr, Mp);
        launch_gemm(lnb, W1 + (size_t)i*512*2048, b1 + (size_t)i*2048, hb, Mp, 2048, 512, false, true);
        launch_gemm(hb,  W2 + (size_t)i*2048*512, b2 + (size_t)i*512,  x,  Mp,  512, 2048, true, false);
    }

    final_fc<<<8,256>>>(x, enw, enb, fcw, fcb, outp, ncls);
}

// round 6
// speedup vs baseline: 1.4447x; 1.3879x over previous
#include <cuda_runtime.h>
#include <cstdint>
#include <math.h>

#define CDIV(a,b) (((a)+(b)-1)/(b))

typedef unsigned long long ull;

// ---- packed fp32x2 helpers (attention kernels) ----
__device__ __forceinline__ void fma2(ull& d, ull a, ull b) {
    asm("fma.rn.f32x2 %0, %1, %2, %0;" : "+l"(d) : "l"(a), "l"(b));
}
__device__ __forceinline__ ull splat2(float x) {
    ull r; unsigned u = __float_as_uint(x);
    asm("mov.b64 %0, {%1, %1};" : "=l"(r) : "r"(u));
    return r;
}
__device__ __forceinline__ float2 unpack2(ull v) {
    unsigned lo, hi;
    asm("mov.b64 {%0, %1}, %2;" : "=r"(lo), "=r"(hi) : "l"(v));
    return make_float2(__uint_as_float(lo), __uint_as_float(hi));
}
__device__ __forceinline__ ull d2u(double d) { return __double_as_longlong(d); }

// ---- tf32 helpers ----
__device__ __forceinline__ float tf32h(float x) {
    uint32_t u;
    asm("cvt.rna.tf32.f32 %0, %1;" : "=r"(u) : "f"(x));
    return __uint_as_float(u);
}
__device__ __forceinline__ void mma8(float* c, const uint32_t* a, uint32_t b0, uint32_t b1) {
    asm volatile("mma.sync.aligned.m16n8k8.row.col.f32.tf32.tf32.f32 "
        "{%0,%1,%2,%3},{%4,%5,%6,%7},{%8,%9},{%0,%1,%2,%3};"
        : "+f"(c[0]), "+f"(c[1]), "+f"(c[2]), "+f"(c[3])
        : "r"(a[0]), "r"(a[1]), "r"(a[2]), "r"(a[3]), "r"(b0), "r"(b1));
}
__device__ __forceinline__ uint32_t smem_u32(const void* p) {
    uint32_t a;
    asm("{ .reg .u64 t; cvta.to.shared.u64 t, %1; cvt.u32.u64 %0, t; }" : "=r"(a) : "l"(p));
    return a;
}
__device__ __forceinline__ void cpa16(uint32_t s, const void* g) {
    asm volatile("cp.async.cg.shared.global [%0], [%1], 16;" :: "r"(s), "l"(g));
}

// ---------------- scratch (static device globals; no runtime alloc) ----------------
__device__ float g_xA [3137*8*512];
__device__ float g_xB [3137*8*512];
__device__ float g_ln [3137*8*512];
__device__ float g_att[3137*8*512];
__device__ float g_qkv[3137*8*1536];
__device__ float g_h  [3137*8*2048];   // also im2col scratch
__device__ int   g_idx[8*8*196*16];
// pre-transposed + tf32-split weights: [N][K] layout
__device__ float g_WtTh[6*1536*512], g_WtTl[6*1536*512];
__device__ float g_WsTh[6*1536*512], g_WsTl[6*1536*512];
__device__ float g_WoTh[6*512*512],  g_WoTl[6*512*512];
__device__ float g_W1Th[6*2048*512], g_W1Tl[6*2048*512];
__device__ float g_W2Th[6*512*2048], g_W2Tl[6*512*2048];
__device__ float g_CvH [512*768],    g_CvL [512*768];

static const int SPAT_SMEM = (2*196*68 + 8*196 + 8*64) * 4;  // 114944 B
#define PAD 36
#define APADF (128*PAD)                 // floats per smem tile
static const int MMA_SMEM = 4*APADF*4;  // 73728 B

// ---------------- HMMA tf32 GEMM (3xTF32 compensated) -------------------------------
// C[M,N] = A[M,K] @ Bt[N,K]^T + bias (+C if ACCUM)(ReLU opt). N%128==0, K%32==0.
// 128 threads = 4 warps, warp tile 64x64, block tile 128x128, k-chunk 32.
template<bool ACCUM, bool RELU>
__global__ __launch_bounds__(128) void gemm_mma(const float* __restrict__ A,
    const float* __restrict__ Bh, const float* __restrict__ Bl,
    const float* __restrict__ bias, float* __restrict__ Cm, int M, int N, int K)
{
    extern __shared__ float sm[];
    float* Ahs = sm;                 // [128][PAD]
    float* Als = sm + APADF;
    float* Bhs = sm + 2*APADF;
    float* Bls = sm + 3*APADF;
    uint32_t sb = smem_u32(sm);

    int tid = threadIdx.x, lane = tid & 31, warp = tid >> 5;
    int bm = blockIdx.y*128, bn = blockIdx.x*128;
    int wm = (warp >> 1)*64, wn = (warp & 1)*64;
    int gid = lane >> 2, tig = lane & 3;

    float acc[4][8][4];
    #pragma unroll
    for (int mt = 0; mt < 4; mt++)
        #pragma unroll
        for (int nt = 0; nt < 8; nt++)
            #pragma unroll
            for (int c = 0; c < 4; c++) acc[mt][nt][c] = 0.f;

    // register-prefetch A chunk 0
    float4 apre[8];
    #pragma unroll
    for (int r = 0; r < 8; r++) {
        int idx = tid + 128*r, row = idx >> 3, c4 = idx & 7;
        apre[r] = (bm + row < M) ? *(const float4*)(A + (size_t)(bm+row)*K + c4*4)
                                 : make_float4(0.f,0.f,0.f,0.f);
    }

    for (int k0 = 0; k0 < K; k0 += 32) {
        // cp.async B hi/lo for this chunk
        #pragma unroll
        for (int r = 0; r < 8; r++) {
            int idx = tid + 128*r, row = idx >> 3, c4 = idx & 7;
            size_t g = (size_t)(bn + row)*K + k0 + c4*4;
            uint32_t so = (uint32_t)(row*PAD + c4*4)*4u;
            cpa16(sb + 2u*APADF*4u + so, Bh + g);
            cpa16(sb + 3u*APADF*4u + so, Bl + g);
        }
        asm volatile("cp.async.commit_group;" ::: "memory");
        // A: tf32 split into smem
        #pragma unroll
        for (int r = 0; r < 8; r++) {
            int idx = tid + 128*r, row = idx >> 3, c4 = idx & 7;
            float4 v = apre[r], h, l;
            h.x = tf32h(v.x); l.x = v.x - h.x;
            h.y = tf32h(v.y); l.y = v.y - h.y;
            h.z = tf32h(v.z); l.z = v.z - h.z;
            h.w = tf32h(v.w); l.w = v.w - h.w;
            int o = row*PAD + c4*4;
            *(float4*)(Ahs + o) = h;
            *(float4*)(Als + o) = l;
        }
        if (k0 + 32 < K) {
            #pragma unroll
            for (int r = 0; r < 8; r++) {
                int idx = tid + 128*r, row = idx >> 3, c4 = idx & 7;
                apre[r] = (bm + row < M)
                    ? *(const float4*)(A + (size_t)(bm+row)*K + k0 + 32 + c4*4)
                    : make_float4(0.f,0.f,0.f,0.f);
            }
        }
        asm volatile("cp.async.wait_group 0;" ::: "memory");
        __syncthreads();

        #pragma unroll
        for (int kk = 0; kk < 32; kk += 8) {
            uint32_t afh[4][4], afl[4][4];
            #pragma unroll
            for (int mt = 0; mt < 4; mt++) {
                int mr = wm + mt*16 + gid;
                afh[mt][0] = __float_as_uint(Ahs[ mr   *PAD + kk + tig]);
                afh[mt][1] = __float_as_uint(Ahs[(mr+8)*PAD + kk + tig]);
                afh[mt][2] = __float_as_uint(Ahs[ mr   *PAD + kk + tig + 4]);
                afh[mt][3] = __float_as_uint(Ahs[(mr+8)*PAD + kk + tig + 4]);
                afl[mt][0] = __float_as_uint(Als[ mr   *PAD + kk + tig]);
                afl[mt][1] = __float_as_uint(Als[(mr+8)*PAD + kk + tig]);
                afl[mt][2] = __float_as_uint(Als[ mr   *PAD + kk + tig + 4]);
                afl[mt][3] = __float_as_uint(Als[(mr+8)*PAD + kk + tig + 4]);
            }
            #pragma unroll
            for (int nt = 0; nt < 8; nt++) {
                int nr = wn + nt*8 + gid;
                uint32_t bh0 = __float_as_uint(Bhs[nr*PAD + kk + tig]);
                uint32_t bh1 = __float_as_uint(Bhs[nr*PAD + kk + tig + 4]);
                uint32_t bl0 = __float_as_uint(Bls[nr*PAD + kk + tig]);
                uint32_t bl1 = __float_as_uint(Bls[nr*PAD + kk + tig + 4]);
                #pragma unroll
                for (int mt = 0; mt < 4; mt++) {
                    mma8(acc[mt][nt], afh[mt], bh0, bh1);
                    mma8(acc[mt][nt], afh[mt], bl0, bl1);
                    mma8(acc[mt][nt], afl[mt], bh0, bh1);
                }
            }
        }
        __syncthreads();
    }

    // ---- epilogue ----
    #pragma unroll
    for (int mt = 0; mt < 4; mt++) {
        #pragma unroll
        for (int nt = 0; nt < 8; nt++) {
            int r0 = bm + wm + mt*16 + gid;
            int col = bn + wn + nt*8 + tig*2;
            float2 bb = *(const float2*)&bias[col];
            if (r0 < M) {
                float2 v = make_float2(acc[mt][nt][0] + bb.x, acc[mt][nt][1] + bb.y);
                if (ACCUM) {
                    float2 o = *(const float2*)&Cm[(size_t)r0*N + col];
                    v.x += o.x; v.y += o.y;
                }
                if (RELU) { v.x = fmaxf(v.x,0.f); v.y = fmaxf(v.y,0.f); }
                *(float2*)&Cm[(size_t)r0*N + col] = v;
            }
            int r1 = r0 + 8;
            if (r1 < M) {
                float2 v = make_float2(acc[mt][nt][2] + bb.x, acc[mt][nt][3] + bb.y);
                if (ACCUM) {
                    float2 o = *(const float2*)&Cm[(size_t)r1*N + col];
                    v.x += o.x; v.y += o.y;
                }
                if (RELU) { v.x = fmaxf(v.x,0.f); v.y = fmaxf(v.y,0.f); }
                *(float2*)&Cm[(size_t)r1*N + col] = v;
            }
        }
    }
}

// ---------------- weight transpose + tf32 split: W[K][N] -> Wh/Wl[N][K] -------------
__global__ void tsplit(const float* __restrict__ W, float* __restrict__ Wh,
                       float* __restrict__ Wl, int K, int N)
{
    __shared__ float t[32][33];
    int l = blockIdx.z;
    const float* Wp = W + (size_t)l*K*N;
    float* Whp = Wh + (size_t)l*K*N;
    float* Wlp = Wl + (size_t)l*K*N;
    int n0 = blockIdx.x*32, k0 = blockIdx.y*32;
    for (int r = threadIdx.y; r < 32; r += 8)
        t[r][threadIdx.x] = Wp[(size_t)(k0+r)*N + n0 + threadIdx.x];
    __syncthreads();
    for (int r = threadIdx.y; r < 32; r += 8) {
        float v = t[threadIdx.x][r];           // = W[k0+tx][n0+r]
        float h = tf32h(v);
        size_t o = (size_t)(n0+r)*K + k0 + threadIdx.x;
        Whp[o] = h; Wlp[o] = v - h;
    }
}

__global__ void split_only(const float* __restrict__ W, float* __restrict__ Wh,
                           float* __restrict__ Wl, int n)
{
    int i = blockIdx.x*256 + threadIdx.x;
    if (i < n) { float v = W[i]; float h = tf32h(v); Wh[i] = h; Wl[i] = v - h; }
}

// ---------------- LayerNorm over C=512, one block per (l,b) row --------------------
__global__ void ln_kernel(const float* __restrict__ in, float* __restrict__ out,
    const float* __restrict__ w, const float* __restrict__ b,
    const float* __restrict__ pos, int rows)
{
    int row = blockIdx.x;
    const float* xr = in + (size_t)row * 512;
    int tid = threadIdx.x;  // 128
    float v[4]; float s = 0.f, s2 = 0.f;
    #pragma unroll
    for (int i = 0; i < 4; i++) {
        float t = xr[tid + 128*i]; v[i] = t; s += t; s2 += t*t;
    }
    #pragma unroll
    for (int o = 16; o; o >>= 1) {
        s  += __shfl_xor_sync(0xffffffffu, s,  o);
        s2 += __shfl_xor_sync(0xffffffffu, s2, o);
    }
    __shared__ float sh0[4], sh1[4];
    int wp = tid >> 5;
    if ((tid & 31) == 0) { sh0[wp] = s; sh1[wp] = s2; }
    __syncthreads();
    s  = sh0[0]+sh0[1]+sh0[2]+sh0[3];
    s2 = sh1[0]+sh1[1]+sh1[2]+sh1[3];
    float mean = s * (1.f/512.f);
    float var  = s2 * (1.f/512.f) - mean*mean;
    float rstd = rsqrtf(var + 1e-5f);
    int l = row >> 3;   // B = 8
    #pragma unroll
    for (int i = 0; i < 4; i++) {
        int c = tid + 128*i;
        float o = (v[i]-mean)*rstd*w[c] + b[c];
        if (pos) o += pos[(size_t)l*512 + c];
        out[(size_t)row*512 + c] = o;
    }
}

// ---------------- CLS attention ----------------------------------------------------
__global__ void cls_attn(const float* __restrict__ qkv, float* __restrict__ att, int L)
{
    int b = blockIdx.x >> 3, h = blockIdx.x & 7;
    __shared__ float p[3137];
    __shared__ float qs[64];
    __shared__ float red[256];
    int tid = threadIdx.x;
    if (tid < 64) qs[tid] = qkv[(size_t)b*1536 + h*64 + tid] * 0.125f;
    __syncthreads();
    float lmax = -1e30f;
    for (int l = tid; l < L; l += 256) {
        const float4* kp = (const float4*)&qkv[((size_t)l*8 + b)*1536 + 512 + h*64];
        const float4* qq = (const float4*)qs;
        float s = 0.f;
        #pragma unroll
        for (int d = 0; d < 16; d++) {
            float4 a = qq[d], k4 = kp[d];
            s += a.x*k4.x + a.y*k4.y + a.z*k4.z + a.w*k4.w;
        }
        p[l] = s; lmax = fmaxf(lmax, s);
    }
    red[tid] = lmax; __syncthreads();
    for (int o = 128; o; o >>= 1) { if (tid < o) red[tid] = fmaxf(red[tid], red[tid+o]); __syncthreads(); }
    float gmax = red[0]; __syncthreads();
    float lsum = 0.f;
    for (int l = tid; l < L; l += 256) { float e = __expf(p[l]-gmax); p[l] = e; lsum += e; }
    red[tid] = lsum; __syncthreads();
    for (int o = 128; o; o >>= 1) { if (tid < o) red[tid] += red[tid+o]; __syncthreads(); }
    float inv = 1.f / red[0];
    __syncthreads();
    int d = tid & 63, g = tid >> 6;
    float acc = 0.f;
    for (int l = g; l < L; l += 4)
        acc += p[l] * qkv[((size_t)l*8 + b)*1536 + 1024 + h*64 + d];
    red[tid] = acc; __syncthreads();
    if (g == 0)
        att[(size_t)b*512 + h*64 + d] = (red[d]+red[64+d]+red[128+d]+red[192+d]) * inv;
}

// ---------------- temporal attention + std top-k pooling ---------------------------
__global__ void temporal_attn(const float* __restrict__ qkv, float* __restrict__ yout,
                              int* __restrict__ idxout, int t, int tp)
{
    int w = blockIdx.x % 196;
    int b = (blockIdx.x / 196) & 7;
    int h = blockIdx.x / (196*8);
    __shared__ float sq[16][64], sk[16][64], sv[16][64];
    __shared__ float sat[16][17];
    __shared__ float ssig[16];
    __shared__ int skeep[16], snew[16];
    int tid = threadIdx.x;  // 128
    for (int i = tid; i < t*64; i += 128) {
        int ti = i >> 6, d = i & 63;
        size_t base = ((size_t)(1 + ti*196 + w)*8 + b)*1536 + h*64 + d;
        sq[ti][d] = qkv[base] * 0.125f;
        sk[ti][d] = qkv[base + 512];
        sv[ti][d] = qkv[base + 1024];
    }
    __syncthreads();
    for (int i = tid; i < t*t; i += 128) {
        int qi = i / t, kj = i % t;
        const double2* qd = (const double2*)sq[qi];
        const double2* kd = (const double2*)sk[kj];
        ull s2 = 0ull;
        #pragma unroll
        for (int d2 = 0; d2 < 16; d2++) {
            double2 qv = qd[d2], kv = kd[d2];
            fma2(s2, d2u(qv.x), d2u(kv.x));
            fma2(s2, d2u(qv.y), d2u(kv.y));
        }
        float2 sf = unpack2(s2);
        sat[qi][kj] = sf.x + sf.y;
    }
    __syncthreads();
    if (tid < t) {
        float m = -1e30f;
        for (int j = 0; j < t; j++) m = fmaxf(m, sat[tid][j]);
        float s = 0.f;
        for (int j = 0; j < t; j++) { float e = expf(sat[tid][j]-m); sat[tid][j] = e; s += e; }
        float inv = 1.f / s;
        float mean = 0.f;
        for (int j = 0; j < t; j++) { float a = sat[tid][j]*inv; sat[tid][j] = a; mean += a; }
        mean /= (float)t;
        float var = 0.f;
        for (int j = 0; j < t; j++) { float d0 = sat[tid][j]-mean; var += d0*d0; }
        ssig[tid] = sqrtf(var / (float)(t-1));
    }
    __syncthreads();
    if (tid < t) {
        float si = ssig[tid]; int r = 0;
        for (int j = 0; j < t; j++)
            if (ssig[j] > si || (ssig[j] == si && j < tid)) r++;
        skeep[tid] = (r < tp) ? 1 : 0;
    }
    __syncthreads();
    if (tid == 0) {
        int c = 0;
        for (int i = 0; i < t; i++)
            if (skeep[i]) { snew[i] = c; idxout[((size_t)(h*8+b)*196 + w)*tp + c] = i; c++; }
    }
    __syncthreads();
    for (int i = tid; i < t*64; i += 128) {
        int qi = i >> 6, d = i & 63;
        if (!skeep[qi]) continue;
        float s = 0.f;
        for (int j = 0; j < t; j++) s += sat[qi][j]*sv[j][d];
        yout[((size_t)(1 + snew[qi]*196 + w)*8 + b)*512 + h*64 + d] = s;
    }
}

// ---------------- spatial attention ------------------------------------------------
__global__ __launch_bounds__(256) void spatial_attn(const float* __restrict__ qkvs,
    float* __restrict__ att, int tp)
{
    int ti = blockIdx.x % tp;
    int b  = (blockIdx.x / tp) & 7;
    int h  = blockIdx.x / (tp*8);
    extern __shared__ float sma[];
    float* Ks = sma;
    float* Vs = Ks + 196*68;
    float* Ps = Vs + 196*68;
    float* Qs = Ps + 8*196;
    int tid = threadIdx.x, lane = tid & 31, warp = tid >> 5;
    for (int i = tid; i < 196*64; i += 256) {
        int w = i >> 6, d = i & 63;
        size_t base = ((size_t)(ti*196 + w)*8 + b)*1536 + h*64 + d;
        Ks[w*68 + d] = qkvs[base + 512];
        Vs[w*68 + d] = qkvs[base + 1024];
    }
    __syncthreads();
    for (int wq = warp; wq < 196; wq += 8) {
        size_t qbase = ((size_t)(ti*196 + wq)*8 + b)*1536 + h*64;
        Qs[warp*64 + lane]      = qkvs[qbase + lane]      * 0.125f;
        Qs[warp*64 + lane + 32] = qkvs[qbase + lane + 32] * 0.125f;
        __syncwarp();
        ull q2[32];
        {
            const double2* qd = (const double2*)(Qs + warp*64);
            #pragma unroll
            for (int i = 0; i < 16; i++) {
                double2 qv = qd[i];
                q2[2*i]   = d2u(qv.x);
                q2[2*i+1] = d2u(qv.y);
            }
        }
        float m = -1e30f;
        float sc[7];
        int nidx = 0;
        for (int kk = lane; kk < 196; kk += 32, nidx++) {
            const double2* kd = (const double2*)(Ks + kk*68);
            ull s2 = 0ull;
            #pragma unroll
            for (int i = 0; i < 16; i++) {
                double2 kv = kd[i];
                fma2(s2, q2[2*i],   d2u(kv.x));
                fma2(s2, q2[2*i+1], d2u(kv.y));
            }
            float2 sf = unpack2(s2);
            float s = sf.x + sf.y;
            sc[nidx] = s; m = fmaxf(m, s);
        }
        #pragma unroll
        for (int o = 16; o; o >>= 1) m = fmaxf(m, __shfl_xor_sync(0xffffffffu, m, o));
        float sum = 0.f; nidx = 0;
        for (int kk = lane; kk < 196; kk += 32, nidx++) {
            float e = __expf(sc[nidx]-m);
            Ps[warp*196 + kk] = e; sum += e;
        }
        #pragma unroll
        for (int o = 16; o; o >>= 1) sum += __shfl_xor_sync(0xffffffffu, sum, o);
        float inv = 1.f / sum;
        __syncwarp();
        ull o2 = 0ull;
        for (int kk = 0; kk < 196; kk++) {
            float pv = Ps[warp*196 + kk];
            ull v2 = *(const ull*)(Vs + kk*68 + 2*lane);
            fma2(o2, splat2(pv), v2);
        }
        float2 of = unpack2(o2);
        size_t obase = ((size_t)(1 + ti*196 + wq)*8 + b)*512 + h*64 + 2*lane;
        *(float2*)&att[obase] = make_float2(of.x*inv, of.y*inv);
        __syncwarp();
    }
}

// ---------------- residual pooling gather ------------------------------------------
__global__ void pool_gather(const float* __restrict__ x, float* __restrict__ xn,
    const int* __restrict__ idx, int tp)
{
    int total = (1 + tp*196)*8*512;
    for (int e = blockIdx.x*blockDim.x + threadIdx.x; e < total; e += gridDim.x*blockDim.x) {
        if (e < 8*512) { xn[e] = x[e]; continue; }
        int c = e & 511;
        int row = e >> 9;
        int b = row & 7;
        int l = row >> 3;
        int lt = l - 1;
        int nt = lt / 196, w = lt % 196;
        int h = c >> 6;
        int st = idx[((size_t)(h*8 + b)*196 + w)*tp + nt];
        xn[e] = x[(((size_t)(1 + st*196 + w)*8 + b) << 9) + c];
    }
}

// ---------------- patch embed helpers ----------------------------------------------
__global__ void im2col_k(const float* __restrict__ src, float* __restrict__ out)
{
    int idx = blockIdx.x*256 + threadIdx.x;
    if (idx >= 25088*768) return;
    int m = idx / 768, k = idx - m*768;
    int b = m & 7; int sp = m >> 3;
    int ti = sp / 196; int p = sp % 196;
    int ph = p / 14, pw = p % 14;
    int ci = k >> 8; int r = k & 255; int kh = r >> 4, kw = r & 15;
    out[idx] = src[(((size_t)(b*3 + ci)*16 + ti)*224 + (ph*16 + kh))*224 + (pw*16 + kw)];
}

__global__ void cls_fill(const float* __restrict__ cls, float* __restrict__ x)
{
    int idx = blockIdx.x*256 + threadIdx.x;
    if (idx < 8*512) x[idx] = cls[idx & 511];
}

// ---------------- final LN (row 0 only) + classifier --------------------------------
__global__ void final_fc(const float* __restrict__ x, const float* __restrict__ enw,
    const float* __restrict__ enb, const float* __restrict__ fcw,
    const float* __restrict__ fcb, float* __restrict__ out, int ncls)
{
    int b = blockIdx.x; int tid = threadIdx.x;   // 256
    __shared__ float xn[512];
    __shared__ float sh0[8], sh1[8];
    float v0 = x[(size_t)b*512 + tid];
    float v1 = x[(size_t)b*512 + tid + 256];
    float s = v0 + v1, s2 = v0*v0 + v1*v1;
    #pragma unroll
    for (int o = 16; o; o >>= 1) {
        s  += __shfl_xor_sync(0xffffffffu, s,  o);
        s2 += __shfl_xor_sync(0xffffffffu, s2, o);
    }
    int wp = tid >> 5;
    if ((tid & 31) == 0) { sh0[wp] = s; sh1[wp] = s2; }
    __syncthreads();
    if (tid == 0) {
        float S = 0.f, S2 = 0.f;
        for (int i = 0; i < 8; i++) { S += sh0[i]; S2 += sh1[i]; }
        sh0[0] = S; sh1[0] = S2;
    }
    __syncthreads();
    float mean = sh0[0]*(1.f/512.f);
    float var  = sh1[0]*(1.f/512.f) - mean*mean;
    float rstd = rsqrtf(var + 1e-5f);
    xn[tid]     = (v0-mean)*rstd*enw[tid]     + enb[tid];
    xn[tid+256] = (v1-mean)*rstd*enw[tid+256] + enb[tid+256];
    __syncthreads();
    for (int n = tid; n < ncls; n += 256) {
        float s3 = fcb[n];
        for (int c = 0; c < 512; c++) s3 += xn[c]*fcw[(size_t)c*ncls + n];
        out[(size_t)b*ncls + n] = s3;
    }
}

// ---------------- host orchestration ------------------------------------------------
static void launch_gemm(const float* A, const float* Bth, const float* Btl,
                        const float* bias, float* Cc,
                        int M, int N, int K, bool accum, bool relu)
{
    dim3 g(N/128, CDIV(M,128));
    if (accum)      gemm_mma<true ,false><<<g,128,MMA_SMEM>>>(A,Bth,Btl,bias,Cc,M,N,K);
    else if (relu)  gemm_mma<false,true ><<<g,128,MMA_SMEM>>>(A,Bth,Btl,bias,Cc,M,N,K);
    else            gemm_mma<false,false><<<g,128,MMA_SMEM>>>(A,Bth,Btl,bias,Cc,M,N,K);
}

extern "C" void kernel_launch(void* const* d_in, const int* in_sizes, int n_in,
                              void* d_out, int out_size)
{
    const float* src   = (const float*)d_in[0];
    const float* convw = (const float*)d_in[1];
    const float* convb = (const float*)d_in[2];
    const float* cls   = (const float*)d_in[3];
    const float* pos   = (const float*)d_in[4];
    const float* Wt    = (const float*)d_in[5];
    const float* bt    = (const float*)d_in[6];
    const float* Ws    = (const float*)d_in[7];
    const float* bs    = (const float*)d_in[8];
    const float* Wo    = (const float*)d_in[9];
    const float* bo    = (const float*)d_in[10];
    const float* n1w   = (const float*)d_in[11];
    const float* n1b   = (const float*)d_in[12];
    const float* n2w   = (const float*)d_in[13];
    const float* n2b   = (const float*)d_in[14];
    const float* W1    = (const float*)d_in[15];
    const float* b1    = (const float*)d_in[16];
    const float* W2    = (const float*)d_in[17];
    const float* b2    = (const float*)d_in[18];
    const float* enw   = (const float*)d_in[19];
    const float* enb   = (const float*)d_in[20];
    const float* fcw   = (const float*)d_in[21];
    const float* fcb   = (const float*)d_in[22];
    float* outp = (float*)d_out;
    int ncls = in_sizes[22];

    void* p;
    cudaGetSymbolAddress(&p, g_xA);  float* xA   = (float*)p;
    cudaGetSymbolAddress(&p, g_xB);  float* xB   = (float*)p;
    cudaGetSymbolAddress(&p, g_ln);  float* lnb  = (float*)p;
    cudaGetSymbolAddress(&p, g_att); float* attb = (float*)p;
    cudaGetSymbolAddress(&p, g_qkv); float* qkvb = (float*)p;
    cudaGetSymbolAddress(&p, g_h);   float* hb   = (float*)p;
    cudaGetSymbolAddress(&p, g_idx); int*   idxb = (int*)p;
    cudaGetSymbolAddress(&p, g_WtTh); float* WtTh = (float*)p;
    cudaGetSymbolAddress(&p, g_WtTl); float* WtTl = (float*)p;
    cudaGetSymbolAddress(&p, g_WsTh); float* WsTh = (float*)p;
    cudaGetSymbolAddress(&p, g_WsTl); float* WsTl = (float*)p;
    cudaGetSymbolAddress(&p, g_WoTh); float* WoTh = (float*)p;
    cudaGetSymbolAddress(&p, g_WoTl); float* WoTl = (float*)p;
    cudaGetSymbolAddress(&p, g_W1Th); float* W1Th = (float*)p;
    cudaGetSymbolAddress(&p, g_W1Tl); float* W1Tl = (float*)p;
    cudaGetSymbolAddress(&p, g_W2Th); float* W2Th = (float*)p;
    cudaGetSymbolAddress(&p, g_W2Tl); float* W2Tl = (float*)p;
    cudaGetSymbolAddress(&p, g_CvH);  float* CvH  = (float*)p;
    cudaGetSymbolAddress(&p, g_CvL);  float* CvL  = (float*)p;

    cudaFuncSetAttribute(spatial_attn, cudaFuncAttributeMaxDynamicSharedMemorySize, SPAT_SMEM);
    cudaFuncSetAttribute(gemm_mma<true ,false>, cudaFuncAttributeMaxDynamicSharedMemorySize, MMA_SMEM);
    cudaFuncSetAttribute(gemm_mma<false,true >, cudaFuncAttributeMaxDynamicSharedMemorySize, MMA_SMEM);
    cudaFuncSetAttribute(gemm_mma<false,false>, cudaFuncAttributeMaxDynamicSharedMemorySize, MMA_SMEM);

    // ---- weight prep: transpose to [N][K] and tf32-split (hi/lo) ----
    dim3 tb(32,8);
    tsplit<<<dim3(1536/32, 512/32, 6), tb>>>(Wt, WtTh, WtTl, 512, 1536);
    tsplit<<<dim3(1536/32, 512/32, 6), tb>>>(Ws, WsTh, WsTl, 512, 1536);
    tsplit<<<dim3( 512/32, 512/32, 6), tb>>>(Wo, WoTh, WoTl, 512, 512);
    tsplit<<<dim3(2048/32, 512/32, 6), tb>>>(W1, W1Th, W1Tl, 512, 2048);
    tsplit<<<dim3( 512/32,2048/32, 6), tb>>>(W2, W2Th, W2Tl, 2048, 512);
    split_only<<<CDIV(512*768,256),256>>>(convw, CvH, CvL, 512*768);  // already [N=512][K=768]

    // ---- patch embed: conv as im2col + GEMM ----
    im2col_k<<<CDIV(25088*768,256),256>>>(src, hb);
    launch_gemm(hb, CvH, CvL, convb, xA + 8*512, 25088, 512, 768, false, false);
    cls_fill<<<CDIV(8*512,256),256>>>(cls, xA);

    float* x  = xA;
    float* xo = xB;
    int t = 16;
    for (int i = 0; i < 6; i++) {
        int pk = (i == 1 || i == 3 || i == 5) ? 2 : 0;
        int tp = t - pk;
        int L = t*196 + 1, M = L*8;

        ln_kernel<<<M,128>>>(x, lnb, n1w + i*512, n1b + i*512, (i == 0) ? pos : nullptr, M);
        launch_gemm(lnb, WtTh + (size_t)i*1536*512, WtTl + (size_t)i*1536*512,
                    bt + (size_t)i*1536, qkvb, M, 1536, 512, false, false);
        cls_attn<<<64,256>>>(qkvb, attb, L);
        temporal_attn<<<8*8*196,128>>>(qkvb, attb, idxb, t, tp);
        int Ms = tp*196*8;
        launch_gemm(attb + 8*512, WsTh + (size_t)i*1536*512, WsTl + (size_t)i*1536*512,
                    bs + (size_t)i*1536, qkvb, Ms, 1536, 512, false, false);
        spatial_attn<<<64*tp,256,SPAT_SMEM>>>(qkvb, attb, tp);

        int Lp = tp*196 + 1, Mp = Lp*8;
        float* xr = x;
        if (pk > 0) {
            pool_gather<<<CDIV(Mp*512,256),256>>>(x, xo, idxb, tp);
            xr = xo;
        }
        launch_gemm(attb, WoTh + (size_t)i*512*512, WoTl + (size_t)i*512*512,
                    bo + (size_t)i*512, xr, Mp, 512, 512, true, false);
        if (pk > 0) { xo = x; x = xr; }
        t = tp;

        ln_kernel<<<Mp,128>>>(x, lnb, n2w + i*512, n2b + i*512, nullptr, Mp);
        launch_gemm(lnb, W1Th + (size_t)i*2048*512, W1Tl + (size_t)i*2048*512,
                    b1 + (size_t)i*2048, hb, Mp, 2048, 512, false, true);
        launch_gemm(hb, W2Th + (size_t)i*512*2048, W2Tl + (size_t)i*512*2048,
                    b2 + (size_t)i*512, x, Mp, 512, 2048, true, false);
    }

    final_fc<<<8,256>>>(x, enw, enb, fcw, fcb, outp, ncls);
}